// round 15
// baseline (speedup 1.0000x reference)
#include <cuda_runtime.h>
#include <cuda_fp16.h>
#include <cstdint>

#define CL 4096
#define CS 4096
#define CE 768
#define CH 12
#define CD 64
#define HSTR 72   // half-row stride: 144B -> 16B-aligned rows, bank-quad pattern 0,4,..28
#define NSPLIT 2  // K-split factor
#define NSTG 5    // KV ring stages (5 => carried-PV stage never collides, mod-5 proof in header)
#define TILES_PER_SPLIT (CS / 64 / NSPLIT)   // 32

static __device__ __host__ constexpr float INV_SCALE = 0.036084391824351614f; // 1/sqrt(768)

// Scratch (no cudaMalloc allowed)
__device__ __half g_Q[CL * CE];
__device__ __half g_K[CS * CE];
__device__ __half g_V[CS * CE];
__device__ __half g_O[CL * CE];
__device__ __half g_X[(size_t)CL * CE * 3];  // fp16 inputs q,k,v
__device__ __half g_W[(size_t)CE * CE * 4];  // fp16 weights Wq,Wk,Wv,Wo
__device__ uint32_t g_MB[(size_t)CL * CS / 32];
__device__ float g_OP[(size_t)NSPLIT * CL * CE];       // partial unnormalized O
__device__ float g_ML[(size_t)NSPLIT * CL * CH * 2];   // per-row (m, l) per split

// ---------------------------------------------------------------------------
__device__ __forceinline__ uint32_t s2u(const void* p) {
    return (uint32_t)__cvta_generic_to_shared(p);
}
__device__ __forceinline__ void cpa(uint32_t d, const void* s) {
    asm volatile("cp.async.cg.shared.global [%0], [%1], 16;" :: "r"(d), "l"(s));
}
__device__ __forceinline__ void cpcommit() {
    asm volatile("cp.async.commit_group;");
}
template <int N> __device__ __forceinline__ void cpwait() {
    asm volatile("cp.async.wait_group %0;" :: "n"(N));
}

__device__ __forceinline__ void ldm4(uint32_t r[4], uint32_t a) {
    asm volatile("ldmatrix.sync.aligned.m8n8.x4.shared.b16 {%0,%1,%2,%3}, [%4];"
                 : "=r"(r[0]), "=r"(r[1]), "=r"(r[2]), "=r"(r[3]) : "r"(a));
}
__device__ __forceinline__ void ldm4t(uint32_t r[4], uint32_t a) {
    asm volatile("ldmatrix.sync.aligned.m8n8.x4.trans.shared.b16 {%0,%1,%2,%3}, [%4];"
                 : "=r"(r[0]), "=r"(r[1]), "=r"(r[2]), "=r"(r[3]) : "r"(a));
}

__device__ __forceinline__ void mma_f16(float c[4], const uint32_t a[4],
                                        uint32_t b0, uint32_t b1) {
    asm volatile(
        "mma.sync.aligned.m16n8k16.row.col.f32.f16.f16.f32 "
        "{%0,%1,%2,%3}, {%4,%5,%6,%7}, {%8,%9}, {%0,%1,%2,%3};\n"
        : "+f"(c[0]), "+f"(c[1]), "+f"(c[2]), "+f"(c[3])
        : "r"(a[0]), "r"(a[1]), "r"(a[2]), "r"(a[3]), "r"(b0), "r"(b1));
}

__device__ __forceinline__ uint32_t packh2(float lo, float hi) {
    __half2 h = __floats2half2_rn(lo, hi);
    return *reinterpret_cast<uint32_t*>(&h);
}

__device__ __forceinline__ float ex2(float x) {
    float r;
    asm("ex2.approx.f32 %0, %1;" : "=f"(r) : "f"(x));
    return r;
}

// p = 2^(praw*C + mn)   all in half2
__device__ __forceinline__ uint32_t exp2h2(uint32_t praw, __half2 c2, __half2 mn2) {
    __half2 t = __hfma2(*reinterpret_cast<__half2*>(&praw), c2, mn2);
    __half2 e = h2exp2(t);
    return *reinterpret_cast<uint32_t*>(&e);
}

// ---------------------------------------------------------------------------
// Convert inputs + weights to fp16. grid (1536, 1, 7); z<3: inputs, z>=3: weights.
// ---------------------------------------------------------------------------
__global__ __launch_bounds__(256) void conv_all(const float* __restrict__ q,
                                                const float* __restrict__ k,
                                                const float* __restrict__ v,
                                                const float* __restrict__ wq,
                                                const float* __restrict__ wk,
                                                const float* __restrict__ wv,
                                                const float* __restrict__ wo,
                                                __half* __restrict__ X,
                                                __half* __restrict__ W)
{
    const int z = blockIdx.z;
    const float* src;
    __half* dst;
    int nblk;
    if (z < 3) {
        src = (z == 0) ? q : (z == 1) ? k : v;
        dst = X + (size_t)z * CL * CE;
        nblk = CL * CE / 2048;
    } else {
        src = (z == 3) ? wq : (z == 4) ? wk : (z == 5) ? wv : wo;
        dst = W + (size_t)(z - 3) * CE * CE;
        nblk = CE * CE / 2048;
    }
    if (blockIdx.x >= nblk) return;
    size_t i = ((size_t)blockIdx.x * 256 + threadIdx.x) * 8;
    float4 v0 = *(const float4*)&src[i];
    float4 v1 = *(const float4*)&src[i + 4];
    uint32_t h[4];
    h[0] = packh2(v0.x, v0.y);
    h[1] = packh2(v0.z, v0.w);
    h[2] = packh2(v1.x, v1.y);
    h[3] = packh2(v1.z, v1.w);
    *(uint4*)&dst[i] = *(uint4*)h;
}

// ---------------------------------------------------------------------------
// Pack mask to bits, vectorized: bit i of word w = mask[w*32+i] != 0
// ---------------------------------------------------------------------------
__global__ __launch_bounds__(256) void pack_mask(const int* __restrict__ m,
                                                 uint32_t* __restrict__ mb) {
    __shared__ uint32_t nib[256];
    int t = threadIdx.x;
    size_t base = (size_t)blockIdx.x * 1024 + (size_t)t * 4;
    int4 v = *(const int4*)&m[base];
    nib[t] = (v.x ? 1u : 0u) | (v.y ? 2u : 0u) | (v.z ? 4u : 0u) | (v.w ? 8u : 0u);
    __syncthreads();
    if (t < 32) {
        uint32_t w = 0;
#pragma unroll
        for (int j = 0; j < 8; j++) w |= nib[t * 8 + j] << (4 * j);
        mb[(size_t)blockIdx.x * 32 + t] = w;
    }
}

// ---------------------------------------------------------------------------
// fp16 GEMM core, cp.async double-buffered + ldmatrix. 128 thr (4 warps),
// CTA tile 128x64, warp 32x64, k-step 64. A[M,768] @ W[768,64-slice].
// ---------------------------------------------------------------------------
__device__ __forceinline__ void gemm_body(const __half* __restrict__ A,
                                          const __half* __restrict__ W,
                                          const float* __restrict__ bias,
                                          float* __restrict__ Cf,
                                          __half* __restrict__ Ch,
                                          int m0, int n0, char* sgc)
{
    __half* smA = (__half*)sgc;             // 2 x 128 x HSTR
    __half* smW = smA + 2 * 128 * HSTR;     // 2 x 64 x HSTR

    const int tid = threadIdx.x;
    const int wid = tid >> 5;
    const int ln  = tid & 31;
    const int gid = ln >> 2;
    const int tig = ln & 3;
    const int qb  = wid * 32;

    const uint32_t aoff0 = (uint32_t)(((qb + (ln & 15)) * HSTR + (ln >> 4) * 8) << 1);
    const uint32_t aoff1 = aoff0 + (16 * HSTR << 1);
    const uint32_t woff  = (uint32_t)(((((ln & 7) + ((ln >> 3) & 1) * 8) * HSTR) + (ln >> 4) * 8) << 1);
    const uint32_t smAu = s2u(smA);
    const uint32_t smWu = s2u(smW);

    auto issue = [&](int k0, int b) {
        __half* dA = smA + b * 128 * HSTR;
        __half* dW = smW + b * 64 * HSTR;
#pragma unroll
        for (int i = 0; i < 8; i++) {
            int lin = tid + i * 128;
            int row = lin >> 3, ch = (lin & 7) * 8;
            cpa(s2u(&dA[row * HSTR + ch]), &A[(size_t)(m0 + row) * CE + k0 + ch]);
        }
#pragma unroll
        for (int i = 0; i < 4; i++) {
            int lin = tid + i * 128;
            int kr = lin >> 3, ch = (lin & 7) * 8;
            cpa(s2u(&dW[kr * HSTR + ch]), &W[(size_t)(k0 + kr) * CE + n0 + ch]);
        }
        cpcommit();
    };

    float c[2][8][4];
#pragma unroll
    for (int m = 0; m < 2; m++)
#pragma unroll
        for (int nf = 0; nf < 8; nf++)
#pragma unroll
            for (int j = 0; j < 4; j++) c[m][nf][j] = 0.f;

    const int NS = CE / 64;  // 12
    issue(0, 0);
    issue(64, 1);

    for (int ks = 0; ks < NS; ks++) {
        const int buf = ks & 1;
        if (ks < NS - 1) cpwait<1>(); else cpwait<0>();
        __syncthreads();

        const uint32_t aBuf = smAu + (uint32_t)(buf * 128 * HSTR * 2);
        const uint32_t wBuf = smWu + (uint32_t)(buf * 64 * HSTR * 2);

#pragma unroll
        for (int g = 0; g < 4; g++) {
            uint32_t a0[4], a1[4];
            ldm4(a0, aBuf + aoff0 + g * 32);
            ldm4(a1, aBuf + aoff1 + g * 32);
#pragma unroll
            for (int np = 0; np < 4; np++) {
                uint32_t b[4];
                ldm4t(b, wBuf + woff + (uint32_t)(g * (16 * HSTR * 2) + np * 32));
                mma_f16(c[0][2 * np],     a0, b[0], b[1]);
                mma_f16(c[0][2 * np + 1], a0, b[2], b[3]);
                mma_f16(c[1][2 * np],     a1, b[0], b[1]);
                mma_f16(c[1][2 * np + 1], a1, b[2], b[3]);
            }
        }
        __syncthreads();
        if (ks + 2 < NS) issue((ks + 2) * 64, buf);
    }

#pragma unroll
    for (int m = 0; m < 2; m++) {
        int r0 = m0 + qb + m * 16 + gid;
        int r1 = r0 + 8;
#pragma unroll
        for (int nf = 0; nf < 8; nf++) {
            int n = n0 + nf * 8 + 2 * tig;
            if (Ch) {
                *(__half2*)&Ch[(size_t)r0 * CE + n] =
                    __floats2half2_rn(c[m][nf][0], c[m][nf][1]);
                *(__half2*)&Ch[(size_t)r1 * CE + n] =
                    __floats2half2_rn(c[m][nf][2], c[m][nf][3]);
            } else {
                float b0v = bias[n], b1v = bias[n + 1];
                *(float2*)&Cf[(size_t)r0 * CE + n] =
                    make_float2(c[m][nf][0] + b0v, c[m][nf][1] + b1v);
                *(float2*)&Cf[(size_t)r1 * CE + n] =
                    make_float2(c[m][nf][2] + b0v, c[m][nf][3] + b1v);
            }
        }
    }
}

__global__ __launch_bounds__(128) void gemm_proj(const __half* __restrict__ X,
                                                 const __half* __restrict__ W,
                                                 __half* __restrict__ Qp,
                                                 __half* __restrict__ Kp,
                                                 __half* __restrict__ Vp)
{
    extern __shared__ char sgc[];
    const int z = blockIdx.z;
    const __half* A = X + (size_t)z * CL * CE;
    const __half* Wz = W + (size_t)z * CE * CE;
    __half* C = (z == 0) ? Qp : (z == 1) ? Kp : Vp;
    gemm_body(A, Wz, nullptr, nullptr, C, blockIdx.y * 128, blockIdx.x * 64, sgc);
}

__global__ __launch_bounds__(128) void gemm_out(const __half* __restrict__ A,
                                                const __half* __restrict__ W,
                                                const float* __restrict__ bias,
                                                float* __restrict__ C)
{
    extern __shared__ char sgc[];
    gemm_body(A, W, bias, C, nullptr, blockIdx.y * 128, blockIdx.x * 64, sgc);
}

// ---------------------------------------------------------------------------
// Flash attention fp16, SPLIT-K + FULL S/PV ROTATION: tile B's probabilities
// are carried across the pair boundary, so EVERY S-mma is interleaved with
// the previous tile's PV-mma; only the softmaxes are exposed. 5-stage ring
// (stage = tile mod 5): reads {t-1, t, t+1}, writes {t+2, t+3} -> all
// distinct mod 5; both written stages finished S and PV last iteration,
// certified by the cpwait->barrier->issue ordering. Pending row-sums are
// absorbed at the next softmax: l = (l + rs)*cr  (== old l*cr + rs order).
// Block = (128 q, head, split), 8 warps x 16 rows.
// ---------------------------------------------------------------------------
__global__ __launch_bounds__(256, 2) void flash_h(const __half* __restrict__ Qg,
                                                  const __half* __restrict__ Kg,
                                                  const __half* __restrict__ Vg,
                                                  const uint32_t* __restrict__ MBg,
                                                  float* __restrict__ OPg,
                                                  float* __restrict__ MLg)
{
    extern __shared__ char smc[];
    __half* Qs = (__half*)smc;              // 128 x HSTR
    __half* Ks = Qs + 128 * HSTR;           // NSTG x 64 x HSTR
    __half* Vs = Ks + NSTG * 64 * HSTR;     // NSTG x 64 x HSTR

    const uint2* MB2 = (const uint2*)MBg;
    const float CEXP = 0.05205889686f;      // INV_SCALE * log2(e)
    const uint32_t ONES2 = 0x3C003C00u;     // half2(1,1)

    const int h  = blockIdx.y;
    const int q0 = blockIdx.x * 128;
    const int z  = blockIdx.z;
    const int tbase = z * TILES_PER_SPLIT;  // first global tile of this split
    const int tid = threadIdx.x;
    const int wid = tid >> 5;
    const int ln  = tid & 31;
    const int gid = ln >> 2;
    const int tig = ln & 3;
    const int qb = wid * 16;

    const uint32_t qBase = s2u(Qs) + (uint32_t)(((qb + (ln & 15)) * HSTR + (ln >> 4) * 8) << 1);
    const uint32_t kOff  = (uint32_t)(((((ln & 7) + ((ln >> 4) & 1) * 8) * HSTR) + ((ln >> 3) & 1) * 8) << 1);
    const uint32_t vOff  = (uint32_t)(((((ln & 7) + ((ln >> 3) & 1) * 8) * HSTR) + (ln >> 4) * 8) << 1);
    const uint32_t KsU = s2u(Ks);
    const uint32_t VsU = s2u(Vs);

    auto issueKV = [&](int k0, int b) {
        __half* dK = Ks + b * 64 * HSTR;
        __half* dV = Vs + b * 64 * HSTR;
#pragma unroll
        for (int i = 0; i < 2; i++) {
            int lin = tid + i * 256;
            int row = lin >> 3, ch = (lin & 7) * 8;
            cpa(s2u(&dK[row * HSTR + ch]), &Kg[(size_t)(k0 + row) * CE + h * CD + ch]);
            cpa(s2u(&dV[row * HSTR + ch]), &Vg[(size_t)(k0 + row) * CE + h * CD + ch]);
        }
        cpcommit();
    };

    float m_i[2] = {-1e30f, -1e30f};   // raw (unscaled) units
    float l_i[2] = {0.f, 0.f};
    float o[8][4];
#pragma unroll
    for (int nf = 0; nf < 8; nf++)
#pragma unroll
        for (int j = 0; j < 4; j++) o[nf][j] = 0.f;

    const int mrow = q0 + qb + gid;

    // one g-step of S = Q @ K^T
    auto s_step = [&](uint32_t kBuf, float s[8][4], int g) {
        uint32_t a[4];
        ldm4(a, qBase + (uint32_t)(g * 32));
#pragma unroll
        for (int np = 0; np < 4; np++) {
            uint32_t b[4];
            ldm4(b, kBuf + kOff + (uint32_t)(np * (16 * HSTR * 2) + g * 32));
            mma_f16(s[2 * np],     a, b[0], b[1]);
            mma_f16(s[2 * np + 1], a, b[2], b[3]);
        }
    };

    // one g-step of O += P @ V, plus the row-sum mma for this g
    auto pv_rs_step = [&](uint32_t vBuf, const uint32_t* ph0, const uint32_t* ph1,
                          float rs[4], int g) {
        uint32_t pa[4] = {ph0[2 * g], ph1[2 * g], ph0[2 * g + 1], ph1[2 * g + 1]};
#pragma unroll
        for (int np = 0; np < 4; np++) {
            uint32_t b[4];
            ldm4t(b, vBuf + vOff + (uint32_t)(g * (16 * HSTR * 2) + np * 32));
            mma_f16(o[2 * np],     pa, b[0], b[1]);
            mma_f16(o[2 * np + 1], pa, b[2], b[3]);
        }
        mma_f16(rs, pa, ONES2, ONES2);
    };

    // softmax: s -> ph; absorbs the pending row-sum, rescales o/l, updates m_i.
    auto softmax = [&](int t, float s[8][4], uint32_t* ph0, uint32_t* ph1,
                       const float rsP[4]) {
        uint2 mw0 = MB2[(size_t)mrow * 64 + t];
        uint2 mw1 = MB2[(size_t)(mrow + 8) * 64 + t];

        float mx0 = -1e30f, mx1 = -1e30f;
#pragma unroll
        for (int nf = 0; nf < 8; nf++) {
            mx0 = fmaxf(mx0, fmaxf(s[nf][0], s[nf][1]));
            mx1 = fmaxf(mx1, fmaxf(s[nf][2], s[nf][3]));
        }
#pragma unroll
        for (int off = 1; off <= 2; off <<= 1) {
            mx0 = fmaxf(mx0, __shfl_xor_sync(0xffffffffu, mx0, off));
            mx1 = fmaxf(mx1, __shfl_xor_sync(0xffffffffu, mx1, off));
        }
        float mn0 = fmaxf(m_i[0], mx0);
        float mn1 = fmaxf(m_i[1], mx1);
        float cr0 = ex2((m_i[0] - mn0) * CEXP);
        float cr1 = ex2((m_i[1] - mn1) * CEXP);
        m_i[0] = mn0;
        m_i[1] = mn1;

        const __half2 C2 = __float2half2_rn(CEXP);
        const __half2 B0 = __float2half2_rn(-mn0 * CEXP);
        const __half2 B1 = __float2half2_rn(-mn1 * CEXP);

#pragma unroll
        for (int nf = 0; nf < 8; nf++) {
            ph0[nf] = exp2h2(packh2(s[nf][0], s[nf][1]), C2, B0);
            ph1[nf] = exp2h2(packh2(s[nf][2], s[nf][3]), C2, B1);
        }

        uint32_t allm = mw0.x & mw0.y & mw1.x & mw1.y;
        if (allm != 0xffffffffu) {
#pragma unroll
            for (int nf = 0; nf < 8; nf++) {
                uint32_t w0 = (nf < 4) ? mw0.x : mw0.y;
                uint32_t w1 = (nf < 4) ? mw1.x : mw1.y;
                int sh = ((nf & 3) << 3) + 2 * tig;
                uint32_t k0m = (((w0 >> sh) & 1) ? 0x0000FFFFu : 0u) |
                               (((w0 >> (sh + 1)) & 1) ? 0xFFFF0000u : 0u);
                uint32_t k1m = (((w1 >> sh) & 1) ? 0x0000FFFFu : 0u) |
                               (((w1 >> (sh + 1)) & 1) ? 0xFFFF0000u : 0u);
                ph0[nf] &= k0m;
                ph1[nf] &= k1m;
            }
        }

        l_i[0] = (l_i[0] + rsP[0]) * cr0;
        l_i[1] = (l_i[1] + rsP[2]) * cr1;
        if (!(cr0 == 1.f && cr1 == 1.f)) {
#pragma unroll
            for (int nf = 0; nf < 8; nf++) {
                o[nf][0] *= cr0; o[nf][1] *= cr0;
                o[nf][2] *= cr1; o[nf][3] *= cr1;
            }
        }
    };

    // prologue: Q + first pair (local tiles 0,1 -> stages 0,1)
#pragma unroll
    for (int i = 0; i < 4; i++) {
        int lin = tid + i * 256;
        int row = lin >> 3, ch = (lin & 7) * 8;
        cpa(s2u(&Qs[row * HSTR + ch]), &Qg[(size_t)(q0 + row) * CE + h * CD + ch]);
    }
    issueKV((tbase + 0) * 64, 0);
    issueKV((tbase + 1) * 64, 1);

    const int NLT = TILES_PER_SPLIT;   // 32 local tiles
    const int NP = NLT / 2;            // 16 pairs

    uint32_t phC0[8], phC1[8];   // carried probs of previous tile B
    uint32_t vBufC = VsU;        // carried V stage (valid from tp=1 on)

    for (int tp = 0; tp < NP; tp++) {
        const int lt0 = tp * 2;

        // Drain MY copies of this pair, THEN barrier (publishes all loads,
        // certifies stages (lt0+2)%5 and (lt0+3)%5 are fully consumed).
        cpwait<0>();
        __syncthreads();

        if (lt0 + 2 < NLT) issueKV((tbase + lt0 + 2) * 64, (lt0 + 2) % NSTG);
        if (lt0 + 3 < NLT) issueKV((tbase + lt0 + 3) * 64, (lt0 + 3) % NSTG);

        const uint32_t kBuf0 = KsU + (uint32_t)((lt0 % NSTG) * 64 * HSTR * 2);
        const uint32_t vBuf0 = VsU + (uint32_t)((lt0 % NSTG) * 64 * HSTR * 2);
        const uint32_t kBuf1 = KsU + (uint32_t)(((lt0 + 1) % NSTG) * 64 * HSTR * 2);
        const uint32_t vBuf1 = VsU + (uint32_t)(((lt0 + 1) % NSTG) * 64 * HSTR * 2);

        // ---- S(A) interleaved with PV(carried prev B) ----
        float sA[8][4];
#pragma unroll
        for (int nf = 0; nf < 8; nf++)
#pragma unroll
            for (int j = 0; j < 4; j++) sA[nf][j] = 0.f;
        float rsP[4] = {0.f, 0.f, 0.f, 0.f};
        if (tp > 0) {
#pragma unroll
            for (int g = 0; g < 4; g++) {
                s_step(kBuf0, sA, g);
                pv_rs_step(vBufC, phC0, phC1, rsP, g);
            }
        } else {
#pragma unroll
            for (int g = 0; g < 4; g++) s_step(kBuf0, sA, g);
        }
        uint32_t phA0[8], phA1[8];
        softmax(tbase + lt0, sA, phA0, phA1, rsP);

        // ---- S(B) interleaved with PV(A) ----
        float sB[8][4];
#pragma unroll
        for (int nf = 0; nf < 8; nf++)
#pragma unroll
            for (int j = 0; j < 4; j++) sB[nf][j] = 0.f;
        float rsA[4] = {0.f, 0.f, 0.f, 0.f};
#pragma unroll
        for (int g = 0; g < 4; g++) {
            s_step(kBuf1, sB, g);
            pv_rs_step(vBuf0, phA0, phA1, rsA, g);
        }
        softmax(tbase + lt0 + 1, sB, phC0, phC1, rsA);  // writes carry directly
        vBufC = vBuf1;
    }

    // tail: PV of the final tile B
    {
        float rsT[4] = {0.f, 0.f, 0.f, 0.f};
#pragma unroll
        for (int g = 0; g < 4; g++)
            pv_rs_step(vBufC, phC0, phC1, rsT, g);
        l_i[0] += rsT[0];
        l_i[1] += rsT[2];
    }

    // epilogue: unnormalized partial O (fp32) + per-row (m, l)
    float* op = OPg + (size_t)z * CL * CE;
    const int r0 = q0 + qb + gid;
#pragma unroll
    for (int nf = 0; nf < 8; nf++) {
        int cc = h * CD + nf * 8 + 2 * tig;
        *(float2*)&op[(size_t)r0 * CE + cc] = make_float2(o[nf][0], o[nf][1]);
        *(float2*)&op[(size_t)(r0 + 8) * CE + cc] = make_float2(o[nf][2], o[nf][3]);
    }
    if (tig == 0) {
        size_t mlb = (((size_t)z * CL + r0) * CH + h) * 2;
        MLg[mlb]     = m_i[0];
        MLg[mlb + 1] = l_i[0];
        size_t mlb1 = (((size_t)z * CL + r0 + 8) * CH + h) * 2;
        MLg[mlb1]     = m_i[1];
        MLg[mlb1 + 1] = l_i[1];
    }
}

// ---------------------------------------------------------------------------
// Combine split-K partials: O = sum_z o_z * 2^((m_z - M)C) / sum_z l_z * 2^((m_z - M)C)
// One thread per 4 columns.
// ---------------------------------------------------------------------------
__global__ __launch_bounds__(256) void flash_combine(const float* __restrict__ OP,
                                                     const float* __restrict__ ML,
                                                     __half* __restrict__ Og)
{
    const float CEXP = 0.05205889686f;
    size_t idx = (size_t)blockIdx.x * 256 + threadIdx.x;   // [0, CL*CE/4)
    int row = (int)(idx / (CE / 4));
    int col = (int)(idx % (CE / 4)) * 4;
    int head = col / CD;

    size_t ml0 = (((size_t)0 * CL + row) * CH + head) * 2;
    size_t ml1 = (((size_t)1 * CL + row) * CH + head) * 2;
    float m1 = ML[ml0], l1 = ML[ml0 + 1];
    float m2 = ML[ml1], l2 = ML[ml1 + 1];
    float M = fmaxf(m1, m2);
    float a1 = ex2((m1 - M) * CEXP);
    float a2 = ex2((m2 - M) * CEXP);
    float L = l1 * a1 + l2 * a2;
    float inv = (L > 0.f) ? (1.f / L) : 0.f;

    float4 o1 = *(const float4*)&OP[(size_t)row * CE + col];
    float4 o2 = *(const float4*)&OP[(size_t)CL * CE + (size_t)row * CE + col];
    uint32_t h01 = packh2((o1.x * a1 + o2.x * a2) * inv, (o1.y * a1 + o2.y * a2) * inv);
    uint32_t h23 = packh2((o1.z * a1 + o2.z * a2) * inv, (o1.w * a1 + o2.w * a2) * inv);
    uint2 outv = make_uint2(h01, h23);
    *(uint2*)&Og[(size_t)row * CE + col] = outv;
}

// ---------------------------------------------------------------------------

extern "C" void kernel_launch(void* const* d_in, const int* in_sizes, int n_in,
                              void* d_out, int out_size)
{
    const float* query = (const float*)d_in[0];
    const float* key   = (const float*)d_in[1];
    const float* value = (const float*)d_in[2];
    const int*   mask  = (const int*)d_in[3];
    const float* Wq    = (const float*)d_in[4];
    const float* Wk    = (const float*)d_in[5];
    const float* Wv    = (const float*)d_in[6];
    const float* Wo    = (const float*)d_in[7];
    const float* bo    = (const float*)d_in[8];
    float* out = (float*)d_out;

    __half *Qp, *Kp, *Vp, *Op, *Xp, *Wp;
    uint32_t* MBp;
    float *OPp, *MLp;
    cudaGetSymbolAddress((void**)&Qp, g_Q);
    cudaGetSymbolAddress((void**)&Kp, g_K);
    cudaGetSymbolAddress((void**)&Vp, g_V);
    cudaGetSymbolAddress((void**)&Op, g_O);
    cudaGetSymbolAddress((void**)&Xp, g_X);
    cudaGetSymbolAddress((void**)&Wp, g_W);
    cudaGetSymbolAddress((void**)&MBp, g_MB);
    cudaGetSymbolAddress((void**)&OPp, g_OP);
    cudaGetSymbolAddress((void**)&MLp, g_ML);

    const int gemm_smem  = (2 * 128 + 2 * 64) * HSTR * 2;            // 55296
    const int flash_smem = (128 + NSTG * 64 * 2) * HSTR * 2;         // 110592

    cudaFuncSetAttribute(gemm_proj, cudaFuncAttributeMaxDynamicSharedMemorySize, gemm_smem);
    cudaFuncSetAttribute(gemm_out, cudaFuncAttributeMaxDynamicSharedMemorySize, gemm_smem);
    cudaFuncSetAttribute(flash_h, cudaFuncAttributeMaxDynamicSharedMemorySize, flash_smem);

    conv_all<<<dim3(CL * CE / 2048, 1, 7), 256>>>(query, key, value,
                                                  Wq, Wk, Wv, Wo, Xp, Wp);

    pack_mask<<<(CL * CS) / 1024, 256>>>(mask, MBp);

    gemm_proj<<<dim3(CE / 64, CL / 128, 3), 128, gemm_smem>>>(Xp, Wp, Qp, Kp, Vp);

    flash_h<<<dim3(CL / 128, CH, NSPLIT), 256, flash_smem>>>(Qp, Kp, Vp, MBp, OPp, MLp);

    flash_combine<<<(CL * CE / 4) / 256, 256>>>(OPp, MLp, Op);

    gemm_out<<<dim3(CE / 64, CL / 128), 128, gemm_smem>>>(
        Op, Wp + (size_t)3 * CE * CE, bo, out);
}

// round 16
// speedup vs baseline: 1.0185x; 1.0185x over previous
#include <cuda_runtime.h>
#include <cuda_fp16.h>
#include <cstdint>

#define CL 4096
#define CS 4096
#define CE 768
#define CH 12
#define CD 64
#define HSTR 72    // half-row stride: 144B, row-step ≡ 4 mod 32 banks
#define WSTR 136   // gemm W-tile stride (128 cols + pad): 272B, ≡ 4 mod 32 banks
#define NSPLIT 2   // K-split factor
#define TILES_PER_SPLIT (CS / 64 / NSPLIT)   // 32

static __device__ __host__ constexpr float INV_SCALE = 0.036084391824351614f; // 1/sqrt(768)

// Scratch (no cudaMalloc allowed)
__device__ __half g_Q[CL * CE];
__device__ __half g_K[CS * CE];
__device__ __half g_V[CS * CE];
__device__ __half g_O[CL * CE];
__device__ __half g_X[(size_t)CL * CE * 3];  // fp16 inputs q,k,v
__device__ __half g_W[(size_t)CE * CE * 4];  // fp16 weights Wq,Wk,Wv,Wo
__device__ uint32_t g_MB[(size_t)CL * CS / 32];
__device__ float g_OP[(size_t)NSPLIT * CL * CE];       // partial unnormalized O
__device__ float g_ML[(size_t)NSPLIT * CL * CH * 2];   // per-row (m, l) per split

// ---------------------------------------------------------------------------
__device__ __forceinline__ uint32_t s2u(const void* p) {
    return (uint32_t)__cvta_generic_to_shared(p);
}
__device__ __forceinline__ void cpa(uint32_t d, const void* s) {
    asm volatile("cp.async.cg.shared.global [%0], [%1], 16;" :: "r"(d), "l"(s));
}
__device__ __forceinline__ void cpcommit() {
    asm volatile("cp.async.commit_group;");
}
template <int N> __device__ __forceinline__ void cpwait() {
    asm volatile("cp.async.wait_group %0;" :: "n"(N));
}

__device__ __forceinline__ void ldm4(uint32_t r[4], uint32_t a) {
    asm volatile("ldmatrix.sync.aligned.m8n8.x4.shared.b16 {%0,%1,%2,%3}, [%4];"
                 : "=r"(r[0]), "=r"(r[1]), "=r"(r[2]), "=r"(r[3]) : "r"(a));
}
__device__ __forceinline__ void ldm4t(uint32_t r[4], uint32_t a) {
    asm volatile("ldmatrix.sync.aligned.m8n8.x4.trans.shared.b16 {%0,%1,%2,%3}, [%4];"
                 : "=r"(r[0]), "=r"(r[1]), "=r"(r[2]), "=r"(r[3]) : "r"(a));
}

__device__ __forceinline__ void mma_f16(float c[4], const uint32_t a[4],
                                        uint32_t b0, uint32_t b1) {
    asm volatile(
        "mma.sync.aligned.m16n8k16.row.col.f32.f16.f16.f32 "
        "{%0,%1,%2,%3}, {%4,%5,%6,%7}, {%8,%9}, {%0,%1,%2,%3};\n"
        : "+f"(c[0]), "+f"(c[1]), "+f"(c[2]), "+f"(c[3])
        : "r"(a[0]), "r"(a[1]), "r"(a[2]), "r"(a[3]), "r"(b0), "r"(b1));
}

__device__ __forceinline__ uint32_t packh2(float lo, float hi) {
    __half2 h = __floats2half2_rn(lo, hi);
    return *reinterpret_cast<uint32_t*>(&h);
}

__device__ __forceinline__ float ex2(float x) {
    float r;
    asm("ex2.approx.f32 %0, %1;" : "=f"(r) : "f"(x));
    return r;
}

// p = 2^(praw*C + mn)   all in half2
__device__ __forceinline__ uint32_t exp2h2(uint32_t praw, __half2 c2, __half2 mn2) {
    __half2 t = __hfma2(*reinterpret_cast<__half2*>(&praw), c2, mn2);
    __half2 e = h2exp2(t);
    return *reinterpret_cast<uint32_t*>(&e);
}

// ---------------------------------------------------------------------------
// Convert inputs + weights to fp16. grid (1536, 1, 7); z<3: inputs, z>=3: weights.
// ---------------------------------------------------------------------------
__global__ __launch_bounds__(256) void conv_all(const float* __restrict__ q,
                                                const float* __restrict__ k,
                                                const float* __restrict__ v,
                                                const float* __restrict__ wq,
                                                const float* __restrict__ wk,
                                                const float* __restrict__ wv,
                                                const float* __restrict__ wo,
                                                __half* __restrict__ X,
                                                __half* __restrict__ W)
{
    const int z = blockIdx.z;
    const float* src;
    __half* dst;
    int nblk;
    if (z < 3) {
        src = (z == 0) ? q : (z == 1) ? k : v;
        dst = X + (size_t)z * CL * CE;
        nblk = CL * CE / 2048;
    } else {
        src = (z == 3) ? wq : (z == 4) ? wk : (z == 5) ? wv : wo;
        dst = W + (size_t)(z - 3) * CE * CE;
        nblk = CE * CE / 2048;
    }
    if (blockIdx.x >= nblk) return;
    size_t i = ((size_t)blockIdx.x * 256 + threadIdx.x) * 8;
    float4 v0 = *(const float4*)&src[i];
    float4 v1 = *(const float4*)&src[i + 4];
    uint32_t h[4];
    h[0] = packh2(v0.x, v0.y);
    h[1] = packh2(v0.z, v0.w);
    h[2] = packh2(v1.x, v1.y);
    h[3] = packh2(v1.z, v1.w);
    *(uint4*)&dst[i] = *(uint4*)h;
}

// ---------------------------------------------------------------------------
// Pack mask to bits, vectorized: bit i of word w = mask[w*32+i] != 0
// ---------------------------------------------------------------------------
__global__ __launch_bounds__(256) void pack_mask(const int* __restrict__ m,
                                                 uint32_t* __restrict__ mb) {
    __shared__ uint32_t nib[256];
    int t = threadIdx.x;
    size_t base = (size_t)blockIdx.x * 1024 + (size_t)t * 4;
    int4 v = *(const int4*)&m[base];
    nib[t] = (v.x ? 1u : 0u) | (v.y ? 2u : 0u) | (v.z ? 4u : 0u) | (v.w ? 8u : 0u);
    __syncthreads();
    if (t < 32) {
        uint32_t w = 0;
#pragma unroll
        for (int j = 0; j < 8; j++) w |= nib[t * 8 + j] << (4 * j);
        mb[(size_t)blockIdx.x * 32 + t] = w;
    }
}

// ---------------------------------------------------------------------------
// fp16 GEMM core: CTA tile 128x128, 256 thr = 8 warps in 4x2 grid, each warp
// 32 rows x 64 cols (the proven per-warp shape). cp.async double-buffered,
// k-step 64. A[M,768] @ W[768, 128-slice].
// ---------------------------------------------------------------------------
__device__ __forceinline__ void gemm_body(const __half* __restrict__ A,
                                          const __half* __restrict__ W,
                                          const float* __restrict__ bias,
                                          float* __restrict__ Cf,
                                          __half* __restrict__ Ch,
                                          int m0, int n0, char* sgc)
{
    __half* smA = (__half*)sgc;             // 2 x 128 x HSTR
    __half* smW = smA + 2 * 128 * HSTR;     // 2 x 64 x WSTR

    const int tid = threadIdx.x;
    const int wid = tid >> 5;
    const int ln  = tid & 31;
    const int gid = ln >> 2;
    const int tig = ln & 3;
    const int qb  = (wid & 3) * 32;   // warp row group
    const int nb  = (wid >> 2) * 64;  // warp col group

    const uint32_t aoff0 = (uint32_t)(((qb + (ln & 15)) * HSTR + (ln >> 4) * 8) << 1);
    const uint32_t aoff1 = aoff0 + (16 * HSTR << 1);
    const uint32_t woff  = (uint32_t)(((((ln & 7) + ((ln >> 3) & 1) * 8) * WSTR) + (ln >> 4) * 8 + nb) << 1);
    const uint32_t smAu = s2u(smA);
    const uint32_t smWu = s2u(smW);

    auto issue = [&](int k0, int b) {
        __half* dA = smA + b * 128 * HSTR;
        __half* dW = smW + b * 64 * WSTR;
#pragma unroll
        for (int i = 0; i < 4; i++) {
            int lin = tid + i * 256;
            int row = lin >> 3, ch = (lin & 7) * 8;
            cpa(s2u(&dA[row * HSTR + ch]), &A[(size_t)(m0 + row) * CE + k0 + ch]);
        }
#pragma unroll
        for (int i = 0; i < 4; i++) {
            int lin = tid + i * 256;
            int kr = lin >> 4, ch = (lin & 15) * 8;
            cpa(s2u(&dW[kr * WSTR + ch]), &W[(size_t)(k0 + kr) * CE + n0 + ch]);
        }
        cpcommit();
    };

    float c[2][8][4];
#pragma unroll
    for (int m = 0; m < 2; m++)
#pragma unroll
        for (int nf = 0; nf < 8; nf++)
#pragma unroll
            for (int j = 0; j < 4; j++) c[m][nf][j] = 0.f;

    const int NS = CE / 64;  // 12
    issue(0, 0);
    issue(64, 1);

    for (int ks = 0; ks < NS; ks++) {
        const int buf = ks & 1;
        if (ks < NS - 1) cpwait<1>(); else cpwait<0>();
        __syncthreads();

        const uint32_t aBuf = smAu + (uint32_t)(buf * 128 * HSTR * 2);
        const uint32_t wBuf = smWu + (uint32_t)(buf * 64 * WSTR * 2);

#pragma unroll
        for (int g = 0; g < 4; g++) {
            uint32_t a0[4], a1[4];
            ldm4(a0, aBuf + aoff0 + g * 32);
            ldm4(a1, aBuf + aoff1 + g * 32);
#pragma unroll
            for (int np = 0; np < 4; np++) {
                uint32_t b[4];
                ldm4t(b, wBuf + woff + (uint32_t)(g * (16 * WSTR * 2) + np * 32));
                mma_f16(c[0][2 * np],     a0, b[0], b[1]);
                mma_f16(c[0][2 * np + 1], a0, b[2], b[3]);
                mma_f16(c[1][2 * np],     a1, b[0], b[1]);
                mma_f16(c[1][2 * np + 1], a1, b[2], b[3]);
            }
        }
        __syncthreads();
        if (ks + 2 < NS) issue((ks + 2) * 64, buf);
    }

#pragma unroll
    for (int m = 0; m < 2; m++) {
        int r0 = m0 + qb + m * 16 + gid;
        int r1 = r0 + 8;
#pragma unroll
        for (int nf = 0; nf < 8; nf++) {
            int n = n0 + nb + nf * 8 + 2 * tig;
            if (Ch) {
                *(__half2*)&Ch[(size_t)r0 * CE + n] =
                    __floats2half2_rn(c[m][nf][0], c[m][nf][1]);
                *(__half2*)&Ch[(size_t)r1 * CE + n] =
                    __floats2half2_rn(c[m][nf][2], c[m][nf][3]);
            } else {
                float b0v = bias[n], b1v = bias[n + 1];
                *(float2*)&Cf[(size_t)r0 * CE + n] =
                    make_float2(c[m][nf][0] + b0v, c[m][nf][1] + b1v);
                *(float2*)&Cf[(size_t)r1 * CE + n] =
                    make_float2(c[m][nf][2] + b0v, c[m][nf][3] + b1v);
            }
        }
    }
}

__global__ __launch_bounds__(256, 2) void gemm_proj(const __half* __restrict__ X,
                                                    const __half* __restrict__ W,
                                                    __half* __restrict__ Qp,
                                                    __half* __restrict__ Kp,
                                                    __half* __restrict__ Vp)
{
    extern __shared__ char sgc[];
    const int z = blockIdx.z;
    const __half* A = X + (size_t)z * CL * CE;
    const __half* Wz = W + (size_t)z * CE * CE;
    __half* C = (z == 0) ? Qp : (z == 1) ? Kp : Vp;
    gemm_body(A, Wz, nullptr, nullptr, C, blockIdx.y * 128, blockIdx.x * 128, sgc);
}

__global__ __launch_bounds__(256, 2) void gemm_out(const __half* __restrict__ A,
                                                   const __half* __restrict__ W,
                                                   const float* __restrict__ bias,
                                                   float* __restrict__ C)
{
    extern __shared__ char sgc[];
    gemm_body(A, W, bias, C, nullptr, blockIdx.y * 128, blockIdx.x * 128, sgc);
}

// ---------------------------------------------------------------------------
// Flash attention fp16 (round-14 structure): SPLIT-K + intra-pair software
// pipelining (S of tile B interleaved with PV of tile A). 4-stage ring,
// proven cpwait->barrier->issue order. fp16 exp2 softmax, tensor-core row
// sums, zero-copy P. Emits unnormalized partial O (fp32) + per-row (m, l).
// Block = (128 q, head, split), 8 warps x 16 rows.
// ---------------------------------------------------------------------------
__global__ __launch_bounds__(256, 2) void flash_h(const __half* __restrict__ Qg,
                                                  const __half* __restrict__ Kg,
                                                  const __half* __restrict__ Vg,
                                                  const uint32_t* __restrict__ MBg,
                                                  float* __restrict__ OPg,
                                                  float* __restrict__ MLg)
{
    extern __shared__ char smc[];
    __half* Qs = (__half*)smc;              // 128 x HSTR
    __half* Ks = Qs + 128 * HSTR;           // 4 x 64 x HSTR
    __half* Vs = Ks + 4 * 64 * HSTR;        // 4 x 64 x HSTR

    const uint2* MB2 = (const uint2*)MBg;
    const float CEXP = 0.05205889686f;      // INV_SCALE * log2(e)
    const uint32_t ONES2 = 0x3C003C00u;     // half2(1,1)

    const int h  = blockIdx.y;
    const int q0 = blockIdx.x * 128;
    const int z  = blockIdx.z;
    const int tbase = z * TILES_PER_SPLIT;
    const int tid = threadIdx.x;
    const int wid = tid >> 5;
    const int ln  = tid & 31;
    const int gid = ln >> 2;
    const int tig = ln & 3;
    const int qb = wid * 16;

    const uint32_t qBase = s2u(Qs) + (uint32_t)(((qb + (ln & 15)) * HSTR + (ln >> 4) * 8) << 1);
    const uint32_t kOff  = (uint32_t)(((((ln & 7) + ((ln >> 4) & 1) * 8) * HSTR) + ((ln >> 3) & 1) * 8) << 1);
    const uint32_t vOff  = (uint32_t)(((((ln & 7) + ((ln >> 3) & 1) * 8) * HSTR) + (ln >> 4) * 8) << 1);
    const uint32_t KsU = s2u(Ks);
    const uint32_t VsU = s2u(Vs);

    auto issueKV = [&](int k0, int b) {
        __half* dK = Ks + b * 64 * HSTR;
        __half* dV = Vs + b * 64 * HSTR;
#pragma unroll
        for (int i = 0; i < 2; i++) {
            int lin = tid + i * 256;
            int row = lin >> 3, ch = (lin & 7) * 8;
            cpa(s2u(&dK[row * HSTR + ch]), &Kg[(size_t)(k0 + row) * CE + h * CD + ch]);
            cpa(s2u(&dV[row * HSTR + ch]), &Vg[(size_t)(k0 + row) * CE + h * CD + ch]);
        }
        cpcommit();
    };

    float m_i[2] = {-1e30f, -1e30f};   // raw (unscaled) units
    float l_i[2] = {0.f, 0.f};
    float o[8][4];
#pragma unroll
    for (int nf = 0; nf < 8; nf++)
#pragma unroll
        for (int j = 0; j < 4; j++) o[nf][j] = 0.f;

    const int mrow = q0 + qb + gid;

    auto s_step = [&](uint32_t kBuf, float s[8][4], int g) {
        uint32_t a[4];
        ldm4(a, qBase + (uint32_t)(g * 32));
#pragma unroll
        for (int np = 0; np < 4; np++) {
            uint32_t b[4];
            ldm4(b, kBuf + kOff + (uint32_t)(np * (16 * HSTR * 2) + g * 32));
            mma_f16(s[2 * np],     a, b[0], b[1]);
            mma_f16(s[2 * np + 1], a, b[2], b[3]);
        }
    };

    auto pv_rs_step = [&](uint32_t vBuf, const uint32_t* ph0, const uint32_t* ph1,
                          float rs[4], int g) {
        uint32_t pa[4] = {ph0[2 * g], ph1[2 * g], ph0[2 * g + 1], ph1[2 * g + 1]};
#pragma unroll
        for (int np = 0; np < 4; np++) {
            uint32_t b[4];
            ldm4t(b, vBuf + vOff + (uint32_t)(g * (16 * HSTR * 2) + np * 32));
            mma_f16(o[2 * np],     pa, b[0], b[1]);
            mma_f16(o[2 * np + 1], pa, b[2], b[3]);
        }
        mma_f16(rs, pa, ONES2, ONES2);
    };

    auto softmax = [&](int t, float s[8][4], uint32_t* ph0, uint32_t* ph1) {
        uint2 mw0 = MB2[(size_t)mrow * 64 + t];
        uint2 mw1 = MB2[(size_t)(mrow + 8) * 64 + t];

        float mx0 = -1e30f, mx1 = -1e30f;
#pragma unroll
        for (int nf = 0; nf < 8; nf++) {
            mx0 = fmaxf(mx0, fmaxf(s[nf][0], s[nf][1]));
            mx1 = fmaxf(mx1, fmaxf(s[nf][2], s[nf][3]));
        }
#pragma unroll
        for (int off = 1; off <= 2; off <<= 1) {
            mx0 = fmaxf(mx0, __shfl_xor_sync(0xffffffffu, mx0, off));
            mx1 = fmaxf(mx1, __shfl_xor_sync(0xffffffffu, mx1, off));
        }
        float mn0 = fmaxf(m_i[0], mx0);
        float mn1 = fmaxf(m_i[1], mx1);
        float cr0 = ex2((m_i[0] - mn0) * CEXP);
        float cr1 = ex2((m_i[1] - mn1) * CEXP);
        m_i[0] = mn0;
        m_i[1] = mn1;

        const __half2 C2 = __float2half2_rn(CEXP);
        const __half2 B0 = __float2half2_rn(-mn0 * CEXP);
        const __half2 B1 = __float2half2_rn(-mn1 * CEXP);

#pragma unroll
        for (int nf = 0; nf < 8; nf++) {
            ph0[nf] = exp2h2(packh2(s[nf][0], s[nf][1]), C2, B0);
            ph1[nf] = exp2h2(packh2(s[nf][2], s[nf][3]), C2, B1);
        }

        uint32_t allm = mw0.x & mw0.y & mw1.x & mw1.y;
        if (allm != 0xffffffffu) {
#pragma unroll
            for (int nf = 0; nf < 8; nf++) {
                uint32_t w0 = (nf < 4) ? mw0.x : mw0.y;
                uint32_t w1 = (nf < 4) ? mw1.x : mw1.y;
                int sh = ((nf & 3) << 3) + 2 * tig;
                uint32_t k0m = (((w0 >> sh) & 1) ? 0x0000FFFFu : 0u) |
                               (((w0 >> (sh + 1)) & 1) ? 0xFFFF0000u : 0u);
                uint32_t k1m = (((w1 >> sh) & 1) ? 0x0000FFFFu : 0u) |
                               (((w1 >> (sh + 1)) & 1) ? 0xFFFF0000u : 0u);
                ph0[nf] &= k0m;
                ph1[nf] &= k1m;
            }
        }

        l_i[0] *= cr0;
        l_i[1] *= cr1;
        if (!(cr0 == 1.f && cr1 == 1.f)) {
#pragma unroll
            for (int nf = 0; nf < 8; nf++) {
                o[nf][0] *= cr0; o[nf][1] *= cr0;
                o[nf][2] *= cr1; o[nf][3] *= cr1;
            }
        }
    };

    // prologue: Q + first pair (local tiles 0,1 -> stages 0,1)
#pragma unroll
    for (int i = 0; i < 4; i++) {
        int lin = tid + i * 256;
        int row = lin >> 3, ch = (lin & 7) * 8;
        cpa(s2u(&Qs[row * HSTR + ch]), &Qg[(size_t)(q0 + row) * CE + h * CD + ch]);
    }
    issueKV((tbase + 0) * 64, 0);
    issueKV((tbase + 1) * 64, 1);

    const int NLT = TILES_PER_SPLIT;   // 32 local tiles
    const int NP = NLT / 2;            // 16 pairs

    for (int tp = 0; tp < NP; tp++) {
        const int lt0 = tp * 2;

        // Drain MY copies of this pair, THEN barrier (publishes all loads,
        // certifies the previous pair's stages are read-done).
        cpwait<0>();
        __syncthreads();

        if (lt0 + 2 < NLT) issueKV((tbase + lt0 + 2) * 64, (lt0 + 2) & 3);
        if (lt0 + 3 < NLT) issueKV((tbase + lt0 + 3) * 64, (lt0 + 3) & 3);

        const uint32_t kBuf0 = KsU + (uint32_t)((lt0 & 3) * 64 * HSTR * 2);
        const uint32_t vBuf0 = VsU + (uint32_t)((lt0 & 3) * 64 * HSTR * 2);
        const uint32_t kBuf1 = KsU + (uint32_t)(((lt0 + 1) & 3) * 64 * HSTR * 2);
        const uint32_t vBuf1 = VsU + (uint32_t)(((lt0 + 1) & 3) * 64 * HSTR * 2);

        // ---- tile A: S ----
        float sA[8][4];
#pragma unroll
        for (int nf = 0; nf < 8; nf++)
#pragma unroll
            for (int j = 0; j < 4; j++) sA[nf][j] = 0.f;
#pragma unroll
        for (int g = 0; g < 4; g++) s_step(kBuf0, sA, g);

        uint32_t phA0[8], phA1[8];
        softmax(tbase + lt0, sA, phA0, phA1);

        // ---- interleave: S(tile B) + PV/rs(tile A) ----
        float sB[8][4];
#pragma unroll
        for (int nf = 0; nf < 8; nf++)
#pragma unroll
            for (int j = 0; j < 4; j++) sB[nf][j] = 0.f;
        float rsA[4] = {0.f, 0.f, 0.f, 0.f};
#pragma unroll
        for (int g = 0; g < 4; g++) {
            s_step(kBuf1, sB, g);
            pv_rs_step(vBuf0, phA0, phA1, rsA, g);
        }
        l_i[0] += rsA[0];
        l_i[1] += rsA[2];

        // ---- tile B: softmax + PV/rs ----
        uint32_t phB0[8], phB1[8];
        softmax(tbase + lt0 + 1, sB, phB0, phB1);
        float rsB[4] = {0.f, 0.f, 0.f, 0.f};
#pragma unroll
        for (int g = 0; g < 4; g++)
            pv_rs_step(vBuf1, phB0, phB1, rsB, g);
        l_i[0] += rsB[0];
        l_i[1] += rsB[2];
    }

    // epilogue: unnormalized partial O (fp32) + per-row (m, l)
    float* op = OPg + (size_t)z * CL * CE;
    const int r0 = q0 + qb + gid;
#pragma unroll
    for (int nf = 0; nf < 8; nf++) {
        int cc = h * CD + nf * 8 + 2 * tig;
        *(float2*)&op[(size_t)r0 * CE + cc] = make_float2(o[nf][0], o[nf][1]);
        *(float2*)&op[(size_t)(r0 + 8) * CE + cc] = make_float2(o[nf][2], o[nf][3]);
    }
    if (tig == 0) {
        size_t mlb = (((size_t)z * CL + r0) * CH + h) * 2;
        MLg[mlb]     = m_i[0];
        MLg[mlb + 1] = l_i[0];
        size_t mlb1 = (((size_t)z * CL + r0 + 8) * CH + h) * 2;
        MLg[mlb1]     = m_i[1];
        MLg[mlb1 + 1] = l_i[1];
    }
}

// ---------------------------------------------------------------------------
// Combine split-K partials: O = sum_z o_z * 2^((m_z - M)C) / sum_z l_z * 2^((m_z - M)C)
// One thread per 4 columns.
// ---------------------------------------------------------------------------
__global__ __launch_bounds__(256) void flash_combine(const float* __restrict__ OP,
                                                     const float* __restrict__ ML,
                                                     __half* __restrict__ Og)
{
    const float CEXP = 0.05205889686f;
    size_t idx = (size_t)blockIdx.x * 256 + threadIdx.x;   // [0, CL*CE/4)
    int row = (int)(idx / (CE / 4));
    int col = (int)(idx % (CE / 4)) * 4;
    int head = col / CD;

    size_t ml0 = (((size_t)0 * CL + row) * CH + head) * 2;
    size_t ml1 = (((size_t)1 * CL + row) * CH + head) * 2;
    float m1 = ML[ml0], l1 = ML[ml0 + 1];
    float m2 = ML[ml1], l2 = ML[ml1 + 1];
    float M = fmaxf(m1, m2);
    float a1 = ex2((m1 - M) * CEXP);
    float a2 = ex2((m2 - M) * CEXP);
    float L = l1 * a1 + l2 * a2;
    float inv = (L > 0.f) ? (1.f / L) : 0.f;

    float4 o1 = *(const float4*)&OP[(size_t)row * CE + col];
    float4 o2 = *(const float4*)&OP[(size_t)CL * CE + (size_t)row * CE + col];
    uint32_t h01 = packh2((o1.x * a1 + o2.x * a2) * inv, (o1.y * a1 + o2.y * a2) * inv);
    uint32_t h23 = packh2((o1.z * a1 + o2.z * a2) * inv, (o1.w * a1 + o2.w * a2) * inv);
    uint2 outv = make_uint2(h01, h23);
    *(uint2*)&Og[(size_t)row * CE + col] = outv;
}

// ---------------------------------------------------------------------------

extern "C" void kernel_launch(void* const* d_in, const int* in_sizes, int n_in,
                              void* d_out, int out_size)
{
    const float* query = (const float*)d_in[0];
    const float* key   = (const float*)d_in[1];
    const float* value = (const float*)d_in[2];
    const int*   mask  = (const int*)d_in[3];
    const float* Wq    = (const float*)d_in[4];
    const float* Wk    = (const float*)d_in[5];
    const float* Wv    = (const float*)d_in[6];
    const float* Wo    = (const float*)d_in[7];
    const float* bo    = (const float*)d_in[8];
    float* out = (float*)d_out;

    __half *Qp, *Kp, *Vp, *Op, *Xp, *Wp;
    uint32_t* MBp;
    float *OPp, *MLp;
    cudaGetSymbolAddress((void**)&Qp, g_Q);
    cudaGetSymbolAddress((void**)&Kp, g_K);
    cudaGetSymbolAddress((void**)&Vp, g_V);
    cudaGetSymbolAddress((void**)&Op, g_O);
    cudaGetSymbolAddress((void**)&Xp, g_X);
    cudaGetSymbolAddress((void**)&Wp, g_W);
    cudaGetSymbolAddress((void**)&MBp, g_MB);
    cudaGetSymbolAddress((void**)&OPp, g_OP);
    cudaGetSymbolAddress((void**)&MLp, g_ML);

    const int gemm_smem  = (2 * 128 * HSTR + 2 * 64 * WSTR) * 2;     // 71680
    const int flash_smem = (128 + 4 * 64 + 4 * 64) * HSTR * 2;       // 92160

    cudaFuncSetAttribute(gemm_proj, cudaFuncAttributeMaxDynamicSharedMemorySize, gemm_smem);
    cudaFuncSetAttribute(gemm_out, cudaFuncAttributeMaxDynamicSharedMemorySize, gemm_smem);
    cudaFuncSetAttribute(flash_h, cudaFuncAttributeMaxDynamicSharedMemorySize, flash_smem);

    conv_all<<<dim3(CL * CE / 2048, 1, 7), 256>>>(query, key, value,
                                                  Wq, Wk, Wv, Wo, Xp, Wp);

    pack_mask<<<(CL * CS) / 1024, 256>>>(mask, MBp);

    gemm_proj<<<dim3(CE / 128, CL / 128, 3), 256, gemm_smem>>>(Xp, Wp, Qp, Kp, Vp);

    flash_h<<<dim3(CL / 128, CH, NSPLIT), 256, flash_smem>>>(Qp, Kp, Vp, MBp, OPp, MLp);

    flash_combine<<<(CL * CE / 4) / 256, 256>>>(OPp, MLp, Op);

    gemm_out<<<dim3(CE / 128, CL / 128), 256, gemm_smem>>>(
        Op, Wp + (size_t)3 * CE * CE, bo, out);
}